// round 8
// baseline (speedup 1.0000x reference)
#include <cuda_runtime.h>
#include <cuda_bf16.h>
#include <math.h>

#define N_PROP   65536
#define N_GT     64
#define NCLS     81
#define TOTAL    512
#define MAX_POS  128
#define TPB      512
#define PPB      256            // proposals per block (2 threads each)
#define NBLK     256            // N_PROP / PPB
#define NWARP    (TPB / 32)

// -------- device scratch --------
__device__ int   g_blk_pos[NBLK];
__device__ int   g_blk_neg[NBLK];
__device__ int   g_sp[NBLK];          // inclusive scan of pos counts (published by scan block)
__device__ int   g_sn[NBLK];          // inclusive scan of neg counts
__device__ int   g_pos_list[TOTAL];   // packed (gt<<16)|i
__device__ int   g_neg_list[TOTAL];
__device__ int   g_non_list[TOTAL];
__device__ float g_ce[TOTAL];
__device__ float g_rg[TOTAL];
// barrier state (separate L2 lines); reset by final reducer
__device__ int          g_cntA[32];
__device__ volatile int g_genA[32];
__device__ int          g_cntB[32];
__device__ volatile int g_genB[32];
__device__ int          g_done;

__device__ __forceinline__ float sl1(float d) {
    float ad = fabsf(d);
    return (ad < 1.0f) ? (0.5f * d * d) : (ad - 0.5f);
}

__global__ void __launch_bounds__(TPB, 2)
k_fused(const float* __restrict__ props,
        const float* __restrict__ gts,
        const int*   __restrict__ gt_labels,
        const float* __restrict__ score,
        const float* __restrict__ txty,
        float* __restrict__ out,
        int n_gt) {
    __shared__ float4 sg[N_GT];
    __shared__ float  sS[N_GT];       // ga + 1e-8 (comparison fold)
    __shared__ float  sga[N_GT];      // raw ga (exact final union)
    __shared__ int    slbl[N_GT];
    __shared__ float  s_ci[PPB], s_cu[PPB];
    __shared__ int    s_cj[PPB];
    __shared__ int    wpc[8], wnc[8];
    __shared__ int    swp[8], swn[8];
    __shared__ int    s_numpos, s_negtot, s_offp, s_offn;
    __shared__ int    s_lastA, s_last;
    __shared__ float  rc[NWARP], rr[NWARP];

    const int t    = threadIdx.x;
    const int bid  = blockIdx.x;
    const int warp = t >> 5, lane = t & 31;
    const int half = t >> 8;                 // 0: gts [0,32), 1: gts [32,64)
    const int lp   = t & (PPB - 1);          // local proposal id
    const unsigned full = 0xffffffffu;

    // ---- stage gt data ----
    if (t < N_GT) {
        float4 g = ((const float4*)gts)[t];
        float ga = (g.z - g.x) * (g.w - g.y);
        sg[t]  = g;
        sga[t] = ga;
        sS[t]  = ga + 1e-8f;
        slbl[t] = gt_labels[t];
    }
    __syncthreads();

    // ============ phase 1: IoU argmax, 4 indep chains x 8 gts ============
    const int i = bid * PPB + lp;
    const float4 p = ((const float4*)props)[i];
    const float pa = (p.z - p.x) * (p.w - p.y);

    const int j0 = half * 32;
    float biA = 0.f, bSA = 1.f, biB = 0.f, bSB = 1.f;
    float biC = 0.f, bSC = 1.f, biD = 0.f, bSD = 1.f;
    int   bjA = j0, bjB = j0 + 8, bjC = j0 + 16, bjD = j0 + 24;
    {   // init each chain with its first gt
        float4 g; float ix, iy;
        g = sg[j0];
        ix = fmaxf(fminf(p.z, g.z) - fmaxf(p.x, g.x), 0.f);
        iy = fmaxf(fminf(p.w, g.w) - fmaxf(p.y, g.y), 0.f);
        biA = ix * iy; bSA = pa + sS[j0];
        g = sg[j0 + 8];
        ix = fmaxf(fminf(p.z, g.z) - fmaxf(p.x, g.x), 0.f);
        iy = fmaxf(fminf(p.w, g.w) - fmaxf(p.y, g.y), 0.f);
        biB = ix * iy; bSB = pa + sS[j0 + 8];
        g = sg[j0 + 16];
        ix = fmaxf(fminf(p.z, g.z) - fmaxf(p.x, g.x), 0.f);
        iy = fmaxf(fminf(p.w, g.w) - fmaxf(p.y, g.y), 0.f);
        biC = ix * iy; bSC = pa + sS[j0 + 16];
        g = sg[j0 + 24];
        ix = fmaxf(fminf(p.z, g.z) - fmaxf(p.x, g.x), 0.f);
        iy = fmaxf(fminf(p.w, g.w) - fmaxf(p.y, g.y), 0.f);
        biD = ix * iy; bSD = pa + sS[j0 + 24];
    }
#pragma unroll
    for (int j = 1; j < 8; j++) {
        int jA = j0 + j, jB = j0 + 8 + j, jC = j0 + 16 + j, jD = j0 + 24 + j;
        float4 gA = sg[jA], gB = sg[jB], gC = sg[jC], gD = sg[jD];
        float SA = pa + sS[jA], SB = pa + sS[jB], SC = pa + sS[jC], SD = pa + sS[jD];
        float ixA = fmaxf(fminf(p.z, gA.z) - fmaxf(p.x, gA.x), 0.f);
        float iyA = fmaxf(fminf(p.w, gA.w) - fmaxf(p.y, gA.y), 0.f);
        float ixB = fmaxf(fminf(p.z, gB.z) - fmaxf(p.x, gB.x), 0.f);
        float iyB = fmaxf(fminf(p.w, gB.w) - fmaxf(p.y, gB.y), 0.f);
        float ixC = fmaxf(fminf(p.z, gC.z) - fmaxf(p.x, gC.x), 0.f);
        float iyC = fmaxf(fminf(p.w, gC.w) - fmaxf(p.y, gC.y), 0.f);
        float ixD = fmaxf(fminf(p.z, gD.z) - fmaxf(p.x, gD.x), 0.f);
        float iyD = fmaxf(fminf(p.w, gD.w) - fmaxf(p.y, gD.y), 0.f);
        float inA = ixA * iyA, inB = ixB * iyB, inC = ixC * iyC, inD = ixD * iyD;
        // iou_new > iou_best  <=>  in*bS > bi*S   (the -inter terms cancel exactly)
        if (inA * bSA > biA * SA) { biA = inA; bSA = SA; bjA = jA; }
        if (inB * bSB > biB * SB) { biB = inB; bSB = SB; bjB = jB; }
        if (inC * bSC > biC * SC) { biC = inC; bSC = SC; bjC = jC; }
        if (inD * bSD > biD * SD) { biD = inD; bSD = SD; bjD = jD; }
    }
    // merge chains (higher-index chain wins only if strictly greater -> first-argmax)
    if (biB * bSA > biA * bSB) { biA = biB; bSA = bSB; bjA = bjB; }
    if (biD * bSC > biC * bSD) { biC = biD; bSC = bSD; bjC = bjD; }
    if (biC * bSA > biA * bSC) { biA = biC; bSA = bSC; bjA = bjC; }

    if (half == 1) { s_ci[lp] = biA; s_cu[lp] = bSA; s_cj[lp] = bjA; }
    __syncthreads();

    int f = 0, bj = bjA;
    unsigned bp = 0, bn = 0;
    if (half == 0) {
        float ui = s_ci[lp], uS = s_cu[lp];
        if (ui * bSA > biA * uS) { biA = ui; bSA = uS; bjA = s_cj[lp]; }
        bj = bjA;
        // exact final iou in reference association order
        float u = ((pa + sga[bj]) - biA) + 1e-8f;
        float miou = biA / u;
        f = (miou >= 0.5f) ? 1 : ((miou >= 0.1f) ? 2 : 0);
        bp = __ballot_sync(full, f == 1);
        bn = __ballot_sync(full, f == 2);
        if (lane == 0) { wpc[warp] = __popc(bp); wnc[warp] = __popc(bn); }
    }
    __syncthreads();
    if (t == 0) {
        int cp = 0, cn = 0;
#pragma unroll
        for (int w = 0; w < 8; w++) { cp += wpc[w]; cn += wnc[w]; }
        g_blk_pos[bid] = cp;
        g_blk_neg[bid] = cn;
    }

    // ============ barrier A: last block performs the scan ============
    __syncthreads();
    if (t == 0) {
        __threadfence();
        s_lastA = (atomicAdd(&g_cntA[0], 1) == NBLK - 1) ? 1 : 0;
    }
    __syncthreads();
    if (s_lastA) {
        // this whole block is available: do the 256-wide scan, publish
        if (t < NBLK) {
            __threadfence();
            int ip  = __ldcg(&g_blk_pos[t]);
            int in_ = __ldcg(&g_blk_neg[t]);
#pragma unroll
            for (int o = 1; o < 32; o <<= 1) {
                int ap = __shfl_up_sync(full, ip, o);
                int an = __shfl_up_sync(full, in_, o);
                if (lane >= o) { ip += ap; in_ += an; }
            }
            if (lane == 31) { swp[warp] = ip; swn[warp] = in_; }
            __syncthreads();
            int basep = 0, basen = 0;
            for (int w = 0; w < warp; w++) { basep += swp[w]; basen += swn[w]; }
            g_sp[t] = basep + ip;
            g_sn[t] = basen + in_;
        } else {
            __syncthreads();
        }
        __syncthreads();
        if (t == 0) {
            __threadfence();
            g_genA[0] = 1;                    // release
        }
    }
    if (t == 0) {
        if (!s_lastA) {
            while (g_genA[0] == 0) { }
            __threadfence();
        }
        // fetch this block's offsets + totals (4 small loads)
        s_offp   = (bid > 0) ? __ldcg(&g_sp[bid - 1]) : 0;
        s_offn   = (bid > 0) ? __ldcg(&g_sn[bid - 1]) : 0;
        s_numpos = min(__ldcg(&g_sp[NBLK - 1]), MAX_POS);
        s_negtot = __ldcg(&g_sn[NBLK - 1]);
    }
    __syncthreads();

    // ============ phase 2b: stable select -> global lists ============
    if (half == 0) {
        int pre_p = 0, pre_n = 0;
        for (int w = 0; w < warp; w++) { pre_p += wpc[w]; pre_n += wnc[w]; }
        unsigned lm = (1u << lane) - 1u;
        int neg_before = pre_n + __popc(bn & lm);
        if (f == 1) {
            int r = s_offp + pre_p + __popc(bp & lm);
            if (r < TOTAL) g_pos_list[r] = i | (bj << 16);
        } else if (f == 2) {
            int r = s_offn + neg_before;
            if (r < TOTAL) g_neg_list[r] = i;
        }
        if (f != 2) {
            int r = (bid * PPB - s_offn) + (lp - neg_before);
            if (r < TOTAL) g_non_list[r] = i;
        }
    }

    // ============ barrier B ============
    __syncthreads();
    if (t == 0) {
        __threadfence();
        if (atomicAdd(&g_cntB[0], 1) == NBLK - 1) {
            __threadfence();
            g_genB[0] = 1;
        } else {
            while (g_genB[0] == 0) { }
            __threadfence();
        }
    }
    __syncthreads();

    // ============ phase 3: loss (2 warps/block -> 512 slots) ============
    if (warp < 2) {
        int slot = bid * 2 + warp;
        int num_pos = s_numpos;
        int neg_total = s_negtot;
        bool is_pos = slot < num_pos;
        int e;
        if (is_pos) e = __ldcg(&g_pos_list[slot]);
        else {
            int j = slot - num_pos;
            e = (j < neg_total) ? __ldcg(&g_neg_list[j])
                                : __ldcg(&g_non_list[j - neg_total]);
        }
        int idx = e & 0xFFFF;
        int g   = e >> 16;
        int lbl = is_pos ? slbl[g] : 0;

        const float* row = score + (size_t)idx * NCLS;
        float v0 = row[lane];
        float v1 = row[lane + 32];
        float v2 = (lane + 64 < NCLS) ? row[lane + 64] : -INFINITY;
        float m = fmaxf(fmaxf(v0, v1), v2);
#pragma unroll
        for (int o = 16; o; o >>= 1) m = fmaxf(m, __shfl_xor_sync(full, m, o));
        float s = expf(v0 - m) + expf(v1 - m) + ((lane + 64 < NCLS) ? expf(v2 - m) : 0.0f);
#pragma unroll
        for (int o = 16; o; o >>= 1) s += __shfl_xor_sync(full, s, o);

        float cand = (lbl < 32) ? v0 : ((lbl < 64) ? v1 : v2);
        float vl = __shfl_sync(full, cand, lbl & 31);

        if (lane == 0) {
            float ce = m + logf(s) - vl;
            float rg = 0.0f;
            if (is_pos) {
                float4 pp = ((const float4*)props)[idx];
                float4 gb = sg[g];
                float pw = pp.z - pp.x, ph = pp.w - pp.y;
                float pcx = pp.x + 0.5f * pw, pcy = pp.y + 0.5f * ph;
                float gw = gb.z - gb.x, gh = gb.w - gb.y;
                float gcx = gb.x + 0.5f * gw, gcy = gb.y + 0.5f * gh;
                float t0 = ((gcx - pcx) / pw) * 10.0f;
                float t1 = ((gcy - pcy) / ph) * 10.0f;
                float t2 = logf(gw / pw) * 5.0f;
                float t3 = logf(gh / ph) * 5.0f;
                float4 pv = *(const float4*)(txty + ((size_t)idx * NCLS + g) * 4);
                rg = sl1(pv.x - t0) + sl1(pv.y - t1) + sl1(pv.z - t2) + sl1(pv.w - t3);
            }
            g_ce[slot] = ce;
            g_rg[slot] = rg;
        }
    }

    // ============ phase 4: last-arriving block reduces, resets state ========
    __syncthreads();
    if (t == 0) {
        __threadfence();
        s_last = (atomicAdd(&g_done, 1) == NBLK - 1) ? 1 : 0;
    }
    __syncthreads();
    if (s_last) {
        __threadfence();
        float c  = __ldcg(&g_ce[t]);
        float r2 = __ldcg(&g_rg[t]);
#pragma unroll
        for (int o = 16; o; o >>= 1) {
            c  += __shfl_xor_sync(full, c, o);
            r2 += __shfl_xor_sync(full, r2, o);
        }
        if (lane == 0) { rc[warp] = c; rr[warp] = r2; }
        __syncthreads();
        if (warp == 0) {
            float cc  = (lane < NWARP) ? rc[lane] : 0.0f;
            float rrv = (lane < NWARP) ? rr[lane] : 0.0f;
#pragma unroll
            for (int o = 8; o; o >>= 1) {
                cc  += __shfl_xor_sync(full, cc, o);
                rrv += __shfl_xor_sync(full, rrv, o);
            }
            if (lane == 0) {
                out[0] = cc  * (1.0f / (float)TOTAL);
                out[1] = rrv * (1.0f / (float)TOTAL);
            }
        }
        // reset barrier state for next graph replay (all blocks are past it)
        if (t == 0) {
            g_cntA[0] = 0; g_cntB[0] = 0;
            g_genA[0] = 0; g_genB[0] = 0;
            g_done    = 0;
        }
    }
}

extern "C" void kernel_launch(void* const* d_in, const int* in_sizes, int n_in,
                              void* d_out, int out_size) {
    const float* props = (const float*)d_in[1];
    const float* score = (const float*)d_in[2];
    const float* txty  = (const float*)d_in[3];
    const float* gts   = (const float*)d_in[4];
    const int*   glbl  = (const int*)d_in[5];
    float* out = (float*)d_out;
    int n_gt = in_sizes[4] / 4;

    k_fused<<<NBLK, TPB>>>(props, gts, glbl, score, txty, out, n_gt);
}